// round 12
// baseline (speedup 1.0000x reference)
#include <cuda_runtime.h>
#include <cuda_fp16.h>
#include <math.h>
#include <stdint.h>

#define BB   8
#define LL   2048
#define DD   256
#define DINx 512
#define NN   64
#define PP   64
#define HH   8
#define NTOK (BB*LL)
#define XDIM 136   /* H + 2N */
#define XPAD 160   /* padded N rows for xproj tensor GEMM (2 tiles of 80) */

typedef unsigned long long u64;

// ---- scratch (static device arrays; no allocation) ----
__device__ float g_u  [NTOK*DINx];
__device__ float g_dbc[NTOK*XDIM];
__device__ float g_y  [NTOK*DINx];

__device__ __half g_x_hi [NTOK*DD];
__device__ __half g_uc_hi[NTOK*DINx];
__device__ __half g_uc_lo[NTOK*DINx];   // scan-only reconstruction
__device__ __half g_yl_hi[NTOK*DINx];

__device__ __half g_wt1_hi[DINx*DD];    // W_in^T  [512,256]
__device__ __half g_wt1_lo[DINx*DD];
__device__ __half g_wt2_hi[XPAD*DINx];  // W_xp^T  [160,512] (rows>=136 zero)
__device__ __half g_wt2_lo[XPAD*DINx];
__device__ __half g_wt3_hi[DD*DINx];    // W_out^T [256,512]
__device__ __half g_wt3_lo[DD*DINx];

// ---- f32x2 packed helpers (scan) ----
__device__ __forceinline__ u64 pack2(float lo, float hi) {
    u64 r; asm("mov.b64 %0, {%1,%2};" : "=l"(r) : "f"(lo), "f"(hi)); return r;
}
__device__ __forceinline__ float2 unpack2(u64 v) {
    float2 r; asm("mov.b64 {%0,%1}, %2;" : "=f"(r.x), "=f"(r.y) : "l"(v)); return r;
}
__device__ __forceinline__ u64 fma2(u64 a, u64 b, u64 c) {
    u64 d; asm("fma.rn.f32x2 %0, %1, %2, %3;" : "=l"(d) : "l"(a), "l"(b), "l"(c)); return d;
}
__device__ __forceinline__ u64 mul2(u64 a, u64 b) {
    u64 d; asm("mul.rn.f32x2 %0, %1, %2;" : "=l"(d) : "l"(a), "l"(b)); return d;
}
__device__ __forceinline__ u64 add2(u64 a, u64 b) {
    u64 d; asm("add.rn.f32x2 %0, %1, %2;" : "=l"(d) : "l"(a), "l"(b)); return d;
}
union F4U { float4 f; ulonglong2 u; };
union F2U { float2 f; u64 u; };

// ---- PTX helpers ----
__device__ __forceinline__ uint32_t smem_u32(const void* p) {
    uint32_t a;
    asm("{ .reg .u64 t; cvta.to.shared.u64 t, %1; cvt.u32.u64 %0, t; }" : "=r"(a) : "l"(p));
    return a;
}
__device__ __forceinline__ void cpasync16(uint32_t dst, const void* src) {
    asm volatile("cp.async.ca.shared.global [%0], [%1], 16;" :: "r"(dst), "l"(src));
}
#define CP_COMMIT() asm volatile("cp.async.commit_group;" ::: "memory")
#define CP_WAIT(n)  asm volatile("cp.async.wait_group %0;" :: "n"(n) : "memory")

__device__ __forceinline__ void ldsm4(uint32_t* r, uint32_t addr) {
    asm volatile("ldmatrix.sync.aligned.m8n8.x4.shared.b16 {%0,%1,%2,%3}, [%4];"
        : "=r"(r[0]), "=r"(r[1]), "=r"(r[2]), "=r"(r[3]) : "r"(addr));
}
__device__ __forceinline__ void ldsm2(uint32_t* r, uint32_t addr) {
    asm volatile("ldmatrix.sync.aligned.m8n8.x2.shared.b16 {%0,%1}, [%2];"
        : "=r"(r[0]), "=r"(r[1]) : "r"(addr));
}
__device__ __forceinline__ void mma_f16(float* c, const uint32_t* a, const uint32_t* b) {
    asm volatile("mma.sync.aligned.m16n8k16.row.col.f32.f16.f16.f32 "
        "{%0,%1,%2,%3}, {%4,%5,%6,%7}, {%8,%9}, {%0,%1,%2,%3};"
        : "+f"(c[0]), "+f"(c[1]), "+f"(c[2]), "+f"(c[3])
        : "r"(a[0]), "r"(a[1]), "r"(a[2]), "r"(a[3]), "r"(b[0]), "r"(b[1]));
}

// ---- fp32 -> fp16 hi/lo split ----
__device__ __forceinline__ void split1h(float v, __half& h, __half& l) {
    h = __float2half_rn(v);
    l = __float2half_rn(v - __half2float(h));
}
__device__ __forceinline__ void store4h(float4 v, __half* hi, size_t eidx) {
    __half2 p0 = __floats2half2_rn(v.x, v.y);
    __half2 p1 = __floats2half2_rn(v.z, v.w);
    uint2 u;
    u.x = *(uint32_t*)&p0; u.y = *(uint32_t*)&p1;
    *(uint2*)(hi + eidx) = u;
}
__device__ __forceinline__ void split4h_store(float4 v, __half* hi, __half* lo, size_t eidx) {
    __half h0,h1,h2,h3,l0,l1,l2,l3;
    split1h(v.x,h0,l0); split1h(v.y,h1,l1); split1h(v.z,h2,l2); split1h(v.w,h3,l3);
    __half2 ph0 = {h0,h1}, ph1 = {h2,h3}, pl0 = {l0,l1}, pl1 = {l2,l3};
    uint2 uh, ul;
    uh.x = *(uint32_t*)&ph0; uh.y = *(uint32_t*)&ph1;
    ul.x = *(uint32_t*)&pl0; ul.y = *(uint32_t*)&pl1;
    *(uint2*)(hi + eidx) = uh;
    *(uint2*)(lo + eidx) = ul;
}

// ============================================================
// LayerNorm: one warp per token; emits fp16 hi only
// ============================================================
template<int D>
__global__ void ln_h_kernel(const float* __restrict__ x, const float* __restrict__ w,
                            const float* __restrict__ b, __half* __restrict__ ohi)
{
    int gw   = (blockIdx.x * blockDim.x + threadIdx.x) >> 5;
    int lane = threadIdx.x & 31;
    if (gw >= NTOK) return;
    constexpr int V4 = D / 128;
    const float4* row = (const float4*)(x + (size_t)gw * D);
    float4 v[V4];
#pragma unroll
    for (int i = 0; i < V4; i++) v[i] = row[i*32 + lane];
    float s = 0.f;
#pragma unroll
    for (int i = 0; i < V4; i++) s += v[i].x + v[i].y + v[i].z + v[i].w;
#pragma unroll
    for (int o = 16; o; o >>= 1) s += __shfl_xor_sync(0xffffffffu, s, o);
    float m = s * (1.0f / D);
    float vs = 0.f;
#pragma unroll
    for (int i = 0; i < V4; i++) {
        float dx;
        dx = v[i].x - m; vs += dx*dx;
        dx = v[i].y - m; vs += dx*dx;
        dx = v[i].z - m; vs += dx*dx;
        dx = v[i].w - m; vs += dx*dx;
    }
#pragma unroll
    for (int o = 16; o; o >>= 1) vs += __shfl_xor_sync(0xffffffffu, vs, o);
    float rs = rsqrtf(vs * (1.0f / D) + 1e-5f);
    const float4* w4 = (const float4*)w;
    const float4* b4 = (const float4*)b;
#pragma unroll
    for (int i = 0; i < V4; i++) {
        float4 wv = w4[i*32 + lane], bv = b4[i*32 + lane], r;
        r.x = (v[i].x - m) * rs * wv.x + bv.x;
        r.y = (v[i].y - m) * rs * wv.y + bv.y;
        r.z = (v[i].z - m) * rs * wv.z + bv.z;
        r.w = (v[i].w - m) * rs * wv.w + bv.w;
        store4h(r, ohi, (size_t)gw * D + i*128 + lane*4);
    }
}

// ============================================================
// Weight prep: Wt[n,k] = W[k,n] (zero-pad n >= N), fp16 hi/lo
// ============================================================
__global__ void prep_w_kernel(const float* __restrict__ W, int K, int N, int NPAD,
                              __half* __restrict__ hi, __half* __restrict__ lo)
{
    int idx = blockIdx.x * blockDim.x + threadIdx.x;
    if (idx >= NPAD * K) return;
    int n = idx / K, k = idx - n * K;
    float v = (n < N) ? W[(size_t)k * N + n] : 0.f;
    __half h, l; split1h(v, h, l);
    hi[idx] = h; lo[idx] = l;
}

// ============================================================
// HMMA fp16 2-product GEMM: C = A_hi @ (B_hi + B_lo)^T (+res)
// A single-split fp16; B hi+lo fp16. CTA 128 x BN, 8 warps,
// KC=32 chunks, cp.async double buffer, single sync/chunk.
// ============================================================
#define KC2 32
#define RPB 80   /* (32+8) fp16 per row = 80 bytes, 16B aligned, conflict-free */

template<int NFPW, int NVALID, bool ADD_RES>
__global__ __launch_bounds__(256, 2) void gemm_mma(
    const __half* __restrict__ A,
    const __half* __restrict__ Bhi, const __half* __restrict__ Blo,
    const float* __restrict__ res, float* __restrict__ C,
    int K, int NLD)
{
    constexpr int BN   = NFPW * 16;
    constexpr int ASEG = 128 * RPB;
    constexpr int BSEG = BN * RPB;
    constexpr int OFFB = 2 * ASEG;

    extern __shared__ __align__(16) char smem[];
    uint32_t sb = smem_u32(smem);

    int tid  = threadIdx.x;
    int lane = tid & 31, wid = tid >> 5;
    int wm = wid >> 1, wn = wid & 1;
    int m0 = blockIdx.y * 128;
    int n0 = blockIdx.x * BN;

    auto loadA = [&](int c, int buf) {
#pragma unroll
        for (int i = 0; i < 2; i++) {
            int e = tid + i*256;           // 512 = 128 rows * 4 chunks16B
            int ch = e & 3, row = e >> 2;
            const __half* src = A + (size_t)(m0 + row)*K + c*KC2 + ch*8;
            uint32_t dst = sb + buf*ASEG + row*RPB + ch*16;
            cpasync16(dst, src);
        }
    };
    auto loadB = [&](int c, int buf) {
        constexpr int TOT = BN * 4 * 2;     // hi + lo
#pragma unroll
        for (int i = 0; i < (TOT + 255)/256; i++) {
            int e = tid + i*256;
            if ((TOT % 256 == 0) || e < TOT) {
                int ch = e & 3; int r2 = e >> 2;
                int sp = (r2 >= BN) ? 1 : 0; int row = r2 - sp*BN;
                const __half* src = (sp ? Blo : Bhi) + (size_t)(n0 + row)*K + c*KC2 + ch*8;
                uint32_t dst = sb + OFFB + (buf*2 + sp)*BSEG + row*RPB + ch*16;
                cpasync16(dst, src);
            }
        }
    };

    float acc[2][NFPW][4];
#pragma unroll
    for (int mf = 0; mf < 2; mf++)
#pragma unroll
        for (int nf = 0; nf < NFPW; nf++)
#pragma unroll
            for (int q = 0; q < 4; q++) acc[mf][nf][q] = 0.f;

    int g = lane >> 3;
    int laneA = ((lane & 7) + ((g & 1) << 3)) * RPB + ((g >> 1) << 4);
    int laneB = ((lane & 7) + ((g >> 1) << 3)) * RPB + ((g & 1) << 4);
    int nwbase = wn * NFPW * 8;

    const int NCH = K / KC2;
    loadA(0, 0); loadB(0, 0); CP_COMMIT();

    for (int c = 0; c < NCH; c++) {
        int buf = c & 1;
        CP_WAIT(0);
        __syncthreads();
        if (c + 1 < NCH) { loadA(c+1, buf^1); loadB(c+1, buf^1); CP_COMMIT(); }
#pragma unroll
        for (int ks = 0; ks < 2; ks++) {
            uint32_t a[2][4];
#pragma unroll
            for (int mf = 0; mf < 2; mf++)
                ldsm4(a[mf], sb + buf*ASEG + (wm*32 + mf*16)*RPB + laneA + ks*32);
#pragma unroll
            for (int np = 0; np < NFPW/2; np++) {
                uint32_t bh[4], bl[4];
                uint32_t ab = sb + OFFB + (buf*2 + 0)*BSEG + (nwbase + np*16)*RPB + laneB + ks*32;
                ldsm4(bh, ab);
                ldsm4(bl, ab + BSEG);
                // product-major, 4 distinct accumulators between revisits
#pragma unroll
                for (int mf = 0; mf < 2; mf++)
#pragma unroll
                    for (int q = 0; q < 2; q++)
                        mma_f16(acc[mf][np*2+q], a[mf], bh + q*2);
#pragma unroll
                for (int mf = 0; mf < 2; mf++)
#pragma unroll
                    for (int q = 0; q < 2; q++)
                        mma_f16(acc[mf][np*2+q], a[mf], bl + q*2);
            }
            if (NFPW & 1) {
                int nf = NFPW - 1;
                uint32_t bh[2], bl[2];
                uint32_t ab = sb + OFFB + (buf*2 + 0)*BSEG + (nwbase + nf*8)*RPB + laneB + ks*32;
                ldsm2(bh, ab);
                ldsm2(bl, ab + BSEG);
#pragma unroll
                for (int mf = 0; mf < 2; mf++) mma_f16(acc[mf][nf], a[mf], bh);
#pragma unroll
                for (int mf = 0; mf < 2; mf++) mma_f16(acc[mf][nf], a[mf], bl);
            }
        }
    }

    // epilogue (registers only)
    int rbase = m0 + wm*32 + (lane >> 2);
    int colb  = n0 + nwbase + (lane & 3)*2;
#pragma unroll
    for (int mf = 0; mf < 2; mf++) {
#pragma unroll
        for (int nf = 0; nf < NFPW; nf++) {
            int col = colb + nf*8;
            if ((NVALID % BN == 0) || col < NVALID) {
                int ra = rbase + mf*16;
                size_t i0 = (size_t)ra * NLD + col;
                size_t i1 = (size_t)(ra + 8) * NLD + col;
                float2 v0 = make_float2(acc[mf][nf][0], acc[mf][nf][1]);
                float2 v1 = make_float2(acc[mf][nf][2], acc[mf][nf][3]);
                if (ADD_RES) {
                    float2 r0 = *(const float2*)(res + i0);
                    float2 r1 = *(const float2*)(res + i1);
                    v0.x += r0.x; v0.y += r0.y;
                    v1.x += r1.x; v1.y += r1.y;
                }
                *(float2*)(C + i0) = v0;
                *(float2*)(C + i1) = v1;
            }
        }
    }
}

// ============================================================
// depthwise conv3 (SAME) + bias + exact GELU; fp16 hi/lo out
// (lo kept for the scan's fp32 reconstruction)
// ============================================================
__global__ void conv_gelu_kernel(const float* __restrict__ cw, const float* __restrict__ cb)
{
    int idx = blockIdx.x * blockDim.x + threadIdx.x;  // NTOK*DINx/4 items
    int c4 = idx & (DINx/4 - 1);
    int r  = idx >> 7;
    int l  = r & (LL - 1);
    int c  = c4 * 4;
    float4 cur  = *((const float4*)(g_u + (size_t)r * DINx) + c4);
    float4 prev = make_float4(0.f,0.f,0.f,0.f);
    float4 next = make_float4(0.f,0.f,0.f,0.f);
    if (l > 0)      prev = *((const float4*)(g_u + (size_t)(r-1) * DINx) + c4);
    if (l < LL - 1) next = *((const float4*)(g_u + (size_t)(r+1) * DINx) + c4);
    float pv[4] = {prev.x, prev.y, prev.z, prev.w};
    float cv[4] = {cur.x,  cur.y,  cur.z,  cur.w};
    float nv[4] = {next.x, next.y, next.z, next.w};
    float ov[4];
#pragma unroll
    for (int j = 0; j < 4; j++) {
        float w0 = cw[(c+j)*3 + 0], w1 = cw[(c+j)*3 + 1], w2 = cw[(c+j)*3 + 2];
        float s = pv[j]*w0 + cv[j]*w1 + nv[j]*w2 + cb[c+j];
        ov[j] = 0.5f * s * (1.0f + erff(s * 0.70710678118654752f));
    }
    float4 o = make_float4(ov[0], ov[1], ov[2], ov[3]);
    split4h_store(o, g_uc_hi, g_uc_lo, (size_t)r * DINx + c);
}

// ============================================================
// SSM scan v3: 128 CTAs = (b, h, p-half), 128 threads.
// ============================================================
#define CHTOK 8
#define NCHS  (LL / CHTOK)
#define BCPITCH 160   /* floats per token: B 4 chunks * 20 + C 4 chunks * 20 */

__global__ __launch_bounds__(128, 1) void scan_kernel(
    const float* __restrict__ dt_bias, const float* __restrict__ A_log,
    const float* __restrict__ Ds)
{
    int blk = blockIdx.x;
    int b  = blk >> 4;
    int h  = (blk >> 1) & 7;
    int ph = blk & 1;
    int tid = threadIdx.x;
    int pl = tid >> 2, nq = tid & 3;
    int p  = ph * 32 + pl;
    size_t base = (size_t)b * LL;
    float Dsh  = Ds[h];
    float dtbh = dt_bias[h];
    float negA = -expf(A_log[h]);

    __shared__ __align__(16) float  sBC[2][CHTOK][BCPITCH];
    __shared__ __align__(16) float  sX [2][CHTOK][32];
    __shared__ __align__(8)  float2 sSc[2][CHTOK][2];

    int tokA = tid >> 5, qA = tid & 31;
    int tokB = (tid + 128) >> 5;                 // tokA + 4
    int dstA = (qA < 16) ? ((qA >> 2)*20 + (qA & 3)*4) : (80 + ((qA-16) >> 2)*20 + ((qA-16) & 3)*4);
    int srcA = (qA < 16) ? (8 + qA*4) : (72 + (qA-16)*4);
    int xtok = tid >> 3, xq = tid & 7;            // tid<64: 8 tok x 8 q

    u64 h2[8];
#pragma unroll
    for (int i = 0; i < 8; i++) h2[i] = 0ULL;

    float4 rA, rB, rX;
    float  rdt = 0.f, rde = 0.f;

#define CHUNK_LOAD(cidx) { size_t rb_ = base + (size_t)(cidx)*CHTOK; \
    rA = *(const float4*)(g_dbc + (rb_ + tokA)*XDIM + srcA); \
    rB = *(const float4*)(g_dbc + (rb_ + tokB)*XDIM + srcA); \
    if (tid < 64) { size_t xo_ = (rb_ + xtok)*DINx + h*PP + ph*32 + xq*4; \
        uint2 xh_ = *(const uint2*)(g_uc_hi + xo_); \
        uint2 xl_ = *(const uint2*)(g_uc_lo + xo_); \
        float2 h0_ = __half22float2(*(__half2*)&xh_.x); \
        float2 h1_ = __half22float2(*(__half2*)&xh_.y); \
        float2 l0_ = __half22float2(*(__half2*)&xl_.x); \
        float2 l1_ = __half22float2(*(__half2*)&xl_.y); \
        rX = make_float4(h0_.x + l0_.x, h0_.y + l0_.y, h1_.x + l1_.x, h1_.y + l1_.y); } \
    if (tid >= 64 && tid < 64 + CHTOK) { int tk_ = tid - 64; \
        float lg_ = g_dbc[(rb_ + tk_)*XDIM + h] + dtbh; \
        float sp_ = (lg_ > 20.f) ? lg_ : log1pf(expf(lg_)); \
        rdt = sp_; rde = expf(negA * sp_); } }

#define CHUNK_STS(bufi) { *(float4*)&sBC[bufi][tokA][dstA] = rA; \
    *(float4*)&sBC[bufi][tokB][dstA] = rB; \
    if (tid < 64) *(float4*)&sX[bufi][xtok][xq*4] = rX; \
    if (tid >= 64 && tid < 64 + CHTOK) { int tk_ = tid - 64; \
        sSc[bufi][tk_][0] = make_float2(rdt, rdt); \
        sSc[bufi][tk_][1] = make_float2(rde, rde); } }

    CHUNK_LOAD(0)
    CHUNK_STS(0)

    for (int c = 0; c < NCHS; c++) {
        int cur = c & 1;
        __syncthreads();
        if (c + 1 < NCHS) { CHUNK_LOAD(c + 1) }
#pragma unroll
        for (int t = 0; t < CHTOK; t++) {
            F4U Bc[4], Cc[4];
#pragma unroll
            for (int j = 0; j < 4; j++) {
                Bc[j].f = *(const float4*)&sBC[cur][t][nq*20 + j*4];
                Cc[j].f = *(const float4*)&sBC[cur][t][80 + nq*20 + j*4];
            }
            float x = sX[cur][t][pl];
            F2U dt2, de2;
            dt2.f = sSc[cur][t][0];
            de2.f = sSc[cur][t][1];
            float dtx = dt2.f.x * x;
            u64 dtx2 = pack2(dtx, dtx);
            u64 dd2  = de2.u;

#pragma unroll
            for (int j = 0; j < 4; j++) {
                h2[2*j+0] = fma2(h2[2*j+0], dd2, mul2(dtx2, Bc[j].u.x));
                h2[2*j+1] = fma2(h2[2*j+1], dd2, mul2(dtx2, Bc[j].u.y));
            }
            u64 y0 = mul2(h2[0], Cc[0].u.x);
            u64 y1 = mul2(h2[2], Cc[1].u.x);
            u64 y2 = mul2(h2[4], Cc[2].u.x);
            u64 y3 = mul2(h2[6], Cc[3].u.x);
            y0 = fma2(h2[1], Cc[0].u.y, y0);
            y1 = fma2(h2[3], Cc[1].u.y, y1);
            y2 = fma2(h2[5], Cc[2].u.y, y2);
            y3 = fma2(h2[7], Cc[3].u.y, y3);
            float2 yf = unpack2(add2(add2(y0, y1), add2(y2, y3)));
            float y = yf.x + yf.y;
            y += __shfl_xor_sync(0xffffffffu, y, 1);
            y += __shfl_xor_sync(0xffffffffu, y, 2);
            if (nq == 0)
                g_y[(base + (size_t)c*CHTOK + t) * DINx + h*PP + p] = y + Dsh * x;
        }
        if (c + 1 < NCHS) { CHUNK_STS(cur ^ 1) }
    }
#undef CHUNK_LOAD
#undef CHUNK_STS
}

// ============================================================
extern "C" void kernel_launch(void* const* d_in, const int* in_sizes, int n_in,
                              void* d_out, int out_size)
{
    const float* src    = (const float*)d_in[0];
    const float* ln_w   = (const float*)d_in[1];
    const float* ln_b   = (const float*)d_in[2];
    const float* W_in   = (const float*)d_in[3];
    const float* conv_w = (const float*)d_in[4];
    const float* conv_b = (const float*)d_in[5];
    const float* W_xp   = (const float*)d_in[6];
    const float* dt_b   = (const float*)d_in[7];
    const float* A_log  = (const float*)d_in[8];
    const float* Ds     = (const float*)d_in[9];
    const float* oln_w  = (const float*)d_in[10];
    const float* oln_b  = (const float*)d_in[11];
    const float* W_out  = (const float*)d_in[12];
    float* out = (float*)d_out;
    (void)in_sizes; (void)n_in; (void)out_size;

    float *pu, *pdbc, *py;
    __half *pxh, *puch, *pylh;
    __half *pw1h, *pw1l, *pw2h, *pw2l, *pw3h, *pw3l;
    cudaGetSymbolAddress((void**)&pu,   g_u);
    cudaGetSymbolAddress((void**)&pdbc, g_dbc);
    cudaGetSymbolAddress((void**)&py,   g_y);
    cudaGetSymbolAddress((void**)&pxh,  g_x_hi);
    cudaGetSymbolAddress((void**)&puch, g_uc_hi);
    cudaGetSymbolAddress((void**)&pylh, g_yl_hi);
    cudaGetSymbolAddress((void**)&pw1h, g_wt1_hi);
    cudaGetSymbolAddress((void**)&pw1l, g_wt1_lo);
    cudaGetSymbolAddress((void**)&pw2h, g_wt2_hi);
    cudaGetSymbolAddress((void**)&pw2l, g_wt2_lo);
    cudaGetSymbolAddress((void**)&pw3h, g_wt3_hi);
    cudaGetSymbolAddress((void**)&pw3l, g_wt3_lo);

    // dynamic smem: 2*ASEG + 4*BSEG
    const int smem128 = 2*128*RPB + 4*128*RPB;   // 61440
    const int smem80  = 2*128*RPB + 4*80*RPB;    // 46080
    cudaFuncSetAttribute(gemm_mma<8,512,false>, cudaFuncAttributeMaxDynamicSharedMemorySize, smem128);
    cudaFuncSetAttribute(gemm_mma<5,136,false>, cudaFuncAttributeMaxDynamicSharedMemorySize, smem80);
    cudaFuncSetAttribute(gemm_mma<8,256,true>,  cudaFuncAttributeMaxDynamicSharedMemorySize, smem128);

    // launch order keeps gemm1 at profiled slot (index 3)
    prep_w_kernel<<<(DINx*DD + 255)/256, 256>>>(W_in, DD, DINx, DINx, pw1h, pw1l);
    prep_w_kernel<<<(XPAD*DINx + 255)/256, 256>>>(W_xp, DINx, XDIM, XPAD, pw2h, pw2l);
    ln_h_kernel<DD><<<NTOK/8, 256>>>(src, ln_w, ln_b, pxh);
    // g_u = x @ W_in  (M=16384, N=512, K=256)   <-- PROFILED SLOT
    gemm_mma<8,512,false><<<dim3(4, NTOK/128), 256, smem128>>>(pxh, pw1h, pw1l, nullptr, pu, DD, DINx);
    conv_gelu_kernel<<<(NTOK*DINx/4)/256, 256>>>(conv_w, conv_b);
    gemm_mma<5,136,false><<<dim3(2, NTOK/128), 256, smem80>>>(puch, pw2h, pw2l, nullptr, pdbc, DINx, XDIM);
    scan_kernel<<<128, 128>>>(dt_b, A_log, Ds);
    prep_w_kernel<<<(DD*DINx + 255)/256, 256>>>(W_out, DINx, DD, DD, pw3h, pw3l);
    ln_h_kernel<DINx><<<NTOK/8, 256>>>(py, oln_w, oln_b, pylh);
    gemm_mma<8,256,true><<<dim3(2, NTOK/128), 256, smem128>>>(pylh, pw3h, pw3l, src, out, DINx, DD);
}

// round 13
// speedup vs baseline: 1.4883x; 1.4883x over previous
#include <cuda_runtime.h>
#include <cuda_bf16.h>
#include <math.h>
#include <stdint.h>

#define BB   8
#define LL   2048
#define DD   256
#define DINx 512
#define NN   64
#define PP   64
#define HH   8
#define NTOK (BB*LL)
#define XDIM 136   /* H + 2N */
#define XPAD 160   /* padded N rows for xproj tensor GEMM (2 tiles of 80) */

typedef unsigned long long u64;

// ---- scratch (static device arrays; no allocation) ----
__device__ float g_u  [NTOK*DINx];
__device__ float g_uc [NTOK*DINx];
__device__ float g_dbc[NTOK*XDIM];
__device__ float g_y  [NTOK*DINx];

__device__ __nv_bfloat16 g_x_hi [NTOK*DD];
__device__ __nv_bfloat16 g_x_lo [NTOK*DD];
__device__ __nv_bfloat16 g_uc_hi[NTOK*DINx];
__device__ __nv_bfloat16 g_uc_lo[NTOK*DINx];
__device__ __nv_bfloat16 g_yl_hi[NTOK*DINx];
__device__ __nv_bfloat16 g_yl_lo[NTOK*DINx];

__device__ __nv_bfloat16 g_wt1_hi[DINx*DD];    // W_in^T  [512,256]
__device__ __nv_bfloat16 g_wt1_lo[DINx*DD];
__device__ __nv_bfloat16 g_wt2_hi[XPAD*DINx];  // W_xp^T  [160,512] (rows>=136 zero)
__device__ __nv_bfloat16 g_wt2_lo[XPAD*DINx];
__device__ __nv_bfloat16 g_wt3_hi[DD*DINx];    // W_out^T [256,512]
__device__ __nv_bfloat16 g_wt3_lo[DD*DINx];

// ---- f32x2 packed helpers (scan) ----
__device__ __forceinline__ u64 pack2(float lo, float hi) {
    u64 r; asm("mov.b64 %0, {%1,%2};" : "=l"(r) : "f"(lo), "f"(hi)); return r;
}
__device__ __forceinline__ float2 unpack2(u64 v) {
    float2 r; asm("mov.b64 {%0,%1}, %2;" : "=f"(r.x), "=f"(r.y) : "l"(v)); return r;
}
__device__ __forceinline__ u64 fma2(u64 a, u64 b, u64 c) {
    u64 d; asm("fma.rn.f32x2 %0, %1, %2, %3;" : "=l"(d) : "l"(a), "l"(b), "l"(c)); return d;
}
__device__ __forceinline__ u64 mul2(u64 a, u64 b) {
    u64 d; asm("mul.rn.f32x2 %0, %1, %2;" : "=l"(d) : "l"(a), "l"(b)); return d;
}
__device__ __forceinline__ u64 add2(u64 a, u64 b) {
    u64 d; asm("add.rn.f32x2 %0, %1, %2;" : "=l"(d) : "l"(a), "l"(b)); return d;
}
union F4U { float4 f; ulonglong2 u; };
union F2U { float2 f; u64 u; };

// ---- PTX helpers ----
__device__ __forceinline__ uint32_t smem_u32(const void* p) {
    uint32_t a;
    asm("{ .reg .u64 t; cvta.to.shared.u64 t, %1; cvt.u32.u64 %0, t; }" : "=r"(a) : "l"(p));
    return a;
}
__device__ __forceinline__ void cpasync16(uint32_t dst, const void* src) {
    asm volatile("cp.async.ca.shared.global [%0], [%1], 16;" :: "r"(dst), "l"(src));
}
#define CP_COMMIT() asm volatile("cp.async.commit_group;" ::: "memory")
#define CP_WAIT(n)  asm volatile("cp.async.wait_group %0;" :: "n"(n) : "memory")

__device__ __forceinline__ void ldsm4(uint32_t* r, uint32_t addr) {
    asm volatile("ldmatrix.sync.aligned.m8n8.x4.shared.b16 {%0,%1,%2,%3}, [%4];"
        : "=r"(r[0]), "=r"(r[1]), "=r"(r[2]), "=r"(r[3]) : "r"(addr));
}
__device__ __forceinline__ void ldsm2(uint32_t* r, uint32_t addr) {
    asm volatile("ldmatrix.sync.aligned.m8n8.x2.shared.b16 {%0,%1}, [%2];"
        : "=r"(r[0]), "=r"(r[1]) : "r"(addr));
}
__device__ __forceinline__ void mma_bf16(float* c, const uint32_t* a, const uint32_t* b) {
    asm volatile("mma.sync.aligned.m16n8k16.row.col.f32.bf16.bf16.f32 "
        "{%0,%1,%2,%3}, {%4,%5,%6,%7}, {%8,%9}, {%0,%1,%2,%3};"
        : "+f"(c[0]), "+f"(c[1]), "+f"(c[2]), "+f"(c[3])
        : "r"(a[0]), "r"(a[1]), "r"(a[2]), "r"(a[3]), "r"(b[0]), "r"(b[1]));
}

// ---- fp32 -> bf16 hi/lo split ----
__device__ __forceinline__ void split1(float v, __nv_bfloat16& h, __nv_bfloat16& l) {
    h = __float2bfloat16(v);
    l = __float2bfloat16(v - __bfloat162float(h));
}
__device__ __forceinline__ void split4_store(float4 v, __nv_bfloat16* hi, __nv_bfloat16* lo, size_t eidx) {
    __nv_bfloat16 h0,h1,h2,h3,l0,l1,l2,l3;
    split1(v.x,h0,l0); split1(v.y,h1,l1); split1(v.z,h2,l2); split1(v.w,h3,l3);
    __nv_bfloat162 ph0 = {h0,h1}, ph1 = {h2,h3}, pl0 = {l0,l1}, pl1 = {l2,l3};
    uint2 uh, ul;
    uh.x = *(uint32_t*)&ph0; uh.y = *(uint32_t*)&ph1;
    ul.x = *(uint32_t*)&pl0; ul.y = *(uint32_t*)&pl1;
    *(uint2*)(hi + eidx) = uh;
    *(uint2*)(lo + eidx) = ul;
}

// ============================================================
// LayerNorm: one warp per token; emits bf16 hi/lo split
// ============================================================
template<int D>
__global__ void ln_split_kernel(const float* __restrict__ x, const float* __restrict__ w,
                                const float* __restrict__ b,
                                __nv_bfloat16* __restrict__ ohi, __nv_bfloat16* __restrict__ olo)
{
    int gw   = (blockIdx.x * blockDim.x + threadIdx.x) >> 5;
    int lane = threadIdx.x & 31;
    if (gw >= NTOK) return;
    constexpr int V4 = D / 128;
    const float4* row = (const float4*)(x + (size_t)gw * D);
    float4 v[V4];
#pragma unroll
    for (int i = 0; i < V4; i++) v[i] = row[i*32 + lane];
    float s = 0.f;
#pragma unroll
    for (int i = 0; i < V4; i++) s += v[i].x + v[i].y + v[i].z + v[i].w;
#pragma unroll
    for (int o = 16; o; o >>= 1) s += __shfl_xor_sync(0xffffffffu, s, o);
    float m = s * (1.0f / D);
    float vs = 0.f;
#pragma unroll
    for (int i = 0; i < V4; i++) {
        float dx;
        dx = v[i].x - m; vs += dx*dx;
        dx = v[i].y - m; vs += dx*dx;
        dx = v[i].z - m; vs += dx*dx;
        dx = v[i].w - m; vs += dx*dx;
    }
#pragma unroll
    for (int o = 16; o; o >>= 1) vs += __shfl_xor_sync(0xffffffffu, vs, o);
    float rs = rsqrtf(vs * (1.0f / D) + 1e-5f);
    const float4* w4 = (const float4*)w;
    const float4* b4 = (const float4*)b;
#pragma unroll
    for (int i = 0; i < V4; i++) {
        float4 wv = w4[i*32 + lane], bv = b4[i*32 + lane], r;
        r.x = (v[i].x - m) * rs * wv.x + bv.x;
        r.y = (v[i].y - m) * rs * wv.y + bv.y;
        r.z = (v[i].z - m) * rs * wv.z + bv.z;
        r.w = (v[i].w - m) * rs * wv.w + bv.w;
        split4_store(r, ohi, olo, (size_t)gw * D + i*128 + lane*4);
    }
}

// ============================================================
// Weight prep: Wt[n,k] = W[k,n] (zero-pad n >= N), bf16 hi/lo
// ============================================================
__global__ void prep_w_kernel(const float* __restrict__ W, int K, int N, int NPAD,
                              __nv_bfloat16* __restrict__ hi, __nv_bfloat16* __restrict__ lo)
{
    int idx = blockIdx.x * blockDim.x + threadIdx.x;
    if (idx >= NPAD * K) return;
    int n = idx / K, k = idx - n * K;
    float v = (n < N) ? W[(size_t)k * N + n] : 0.f;
    __nv_bfloat16 h, l; split1(v, h, l);
    hi[idx] = h; lo[idx] = l;
}

// ============================================================
// HMMA bf16x3 GEMM: C[M,NVALID] = A[M,K] @ Bt[BN,K]^T (+res)
// CTA 128 x BN (BN = NFPW*16), 8 warps (4M x 2N), KC=32 chunks,
// cp.async double buffer, single sync/chunk, occupancy 2,
// product-major MMA ordering.
// ============================================================
#define KC2 32
#define RPB 80   /* (32+8) bf16 per row = 80 bytes, 16B aligned, conflict-free */

template<int NFPW, int NVALID, bool ADD_RES>
__global__ __launch_bounds__(256, 2) void gemm_mma(
    const __nv_bfloat16* __restrict__ Ahi, const __nv_bfloat16* __restrict__ Alo,
    const __nv_bfloat16* __restrict__ Bhi, const __nv_bfloat16* __restrict__ Blo,
    const float* __restrict__ res, float* __restrict__ C,
    int K, int NLD)
{
    constexpr int BN   = NFPW * 16;
    constexpr int ASEG = 128 * RPB;
    constexpr int BSEG = BN * RPB;
    constexpr int OFFB = 4 * ASEG;

    extern __shared__ __align__(16) char smem[];
    uint32_t sb = smem_u32(smem);

    int tid  = threadIdx.x;
    int lane = tid & 31, wid = tid >> 5;
    int wm = wid >> 1, wn = wid & 1;
    int m0 = blockIdx.y * 128;
    int n0 = blockIdx.x * BN;

    auto loadA = [&](int c, int buf) {
#pragma unroll
        for (int i = 0; i < 4; i++) {
            int e = tid + i*256;           // 1024 = 128 rows * 4 ch * 2 splits
            int ch = e & 3, row = (e >> 2) & 127, sp = e >> 9;
            const __nv_bfloat16* src = (sp ? Alo : Ahi) + (size_t)(m0 + row)*K + c*KC2 + ch*8;
            uint32_t dst = sb + (buf*2 + sp)*ASEG + row*RPB + ch*16;
            cpasync16(dst, src);
        }
    };
    auto loadB = [&](int c, int buf) {
        constexpr int TOT = BN * 4 * 2;
#pragma unroll
        for (int i = 0; i < (TOT + 255)/256; i++) {
            int e = tid + i*256;
            if ((TOT % 256 == 0) || e < TOT) {
                int ch = e & 3; int r2 = e >> 2;
                int sp = (r2 >= BN) ? 1 : 0; int row = r2 - sp*BN;
                const __nv_bfloat16* src = (sp ? Blo : Bhi) + (size_t)(n0 + row)*K + c*KC2 + ch*8;
                uint32_t dst = sb + OFFB + (buf*2 + sp)*BSEG + row*RPB + ch*16;
                cpasync16(dst, src);
            }
        }
    };

    float acc[2][NFPW][4];
#pragma unroll
    for (int mf = 0; mf < 2; mf++)
#pragma unroll
        for (int nf = 0; nf < NFPW; nf++)
#pragma unroll
            for (int q = 0; q < 4; q++) acc[mf][nf][q] = 0.f;

    int g = lane >> 3;
    int laneA = ((lane & 7) + ((g & 1) << 3)) * RPB + ((g >> 1) << 4);
    int laneB = ((lane & 7) + ((g >> 1) << 3)) * RPB + ((g & 1) << 4);
    int nwbase = wn * NFPW * 8;

    const int NCH = K / KC2;
    loadA(0, 0); loadB(0, 0); CP_COMMIT();

    for (int c = 0; c < NCH; c++) {
        int buf = c & 1;
        CP_WAIT(0);
        __syncthreads();
        if (c + 1 < NCH) { loadA(c+1, buf^1); loadB(c+1, buf^1); CP_COMMIT(); }
#pragma unroll
        for (int ks = 0; ks < 2; ks++) {
            uint32_t a[2][2][4];
#pragma unroll
            for (int mf = 0; mf < 2; mf++)
#pragma unroll
                for (int sp = 0; sp < 2; sp++)
                    ldsm4(a[mf][sp], sb + (buf*2 + sp)*ASEG + (wm*32 + mf*16)*RPB + laneA + ks*32);
#pragma unroll
            for (int np = 0; np < NFPW/2; np++) {
                uint32_t bh[4], bl[4];
                uint32_t ab = sb + OFFB + (buf*2 + 0)*BSEG + (nwbase + np*16)*RPB + laneB + ks*32;
                ldsm4(bh, ab);
                ldsm4(bl, ab + BSEG);
                // product-major: 4 distinct accumulators between revisits
#pragma unroll
                for (int mf = 0; mf < 2; mf++)
#pragma unroll
                    for (int q = 0; q < 2; q++)
                        mma_bf16(acc[mf][np*2+q], a[mf][0], bh + q*2);
#pragma unroll
                for (int mf = 0; mf < 2; mf++)
#pragma unroll
                    for (int q = 0; q < 2; q++)
                        mma_bf16(acc[mf][np*2+q], a[mf][0], bl + q*2);
#pragma unroll
                for (int mf = 0; mf < 2; mf++)
#pragma unroll
                    for (int q = 0; q < 2; q++)
                        mma_bf16(acc[mf][np*2+q], a[mf][1], bh + q*2);
            }
            if (NFPW & 1) {
                int nf = NFPW - 1;
                uint32_t bh[2], bl[2];
                uint32_t ab = sb + OFFB + (buf*2 + 0)*BSEG + (nwbase + nf*8)*RPB + laneB + ks*32;
                ldsm2(bh, ab);
                ldsm2(bl, ab + BSEG);
#pragma unroll
                for (int mf = 0; mf < 2; mf++) mma_bf16(acc[mf][nf], a[mf][0], bh);
#pragma unroll
                for (int mf = 0; mf < 2; mf++) mma_bf16(acc[mf][nf], a[mf][0], bl);
#pragma unroll
                for (int mf = 0; mf < 2; mf++) mma_bf16(acc[mf][nf], a[mf][1], bh);
            }
        }
    }

    // epilogue (registers only)
    int rbase = m0 + wm*32 + (lane >> 2);
    int colb  = n0 + nwbase + (lane & 3)*2;
#pragma unroll
    for (int mf = 0; mf < 2; mf++) {
#pragma unroll
        for (int nf = 0; nf < NFPW; nf++) {
            int col = colb + nf*8;
            if ((NVALID % BN == 0) || col < NVALID) {
                int ra = rbase + mf*16;
                size_t i0 = (size_t)ra * NLD + col;
                size_t i1 = (size_t)(ra + 8) * NLD + col;
                float2 v0 = make_float2(acc[mf][nf][0], acc[mf][nf][1]);
                float2 v1 = make_float2(acc[mf][nf][2], acc[mf][nf][3]);
                if (ADD_RES) {
                    float2 r0 = *(const float2*)(res + i0);
                    float2 r1 = *(const float2*)(res + i1);
                    v0.x += r0.x; v0.y += r0.y;
                    v1.x += r1.x; v1.y += r1.y;
                }
                *(float2*)(C + i0) = v0;
                *(float2*)(C + i1) = v1;
            }
        }
    }
}

// ============================================================
// depthwise conv3 (SAME) + bias + exact GELU
// writes fp32 g_uc (for the scan) AND bf16 hi/lo (for xproj GEMM)
// ============================================================
__global__ void conv_gelu_kernel(const float* __restrict__ cw, const float* __restrict__ cb)
{
    int idx = blockIdx.x * blockDim.x + threadIdx.x;  // NTOK*DINx/4 items
    int c4 = idx & (DINx/4 - 1);
    int r  = idx >> 7;
    int l  = r & (LL - 1);
    int c  = c4 * 4;
    float4 cur  = *((const float4*)(g_u + (size_t)r * DINx) + c4);
    float4 prev = make_float4(0.f,0.f,0.f,0.f);
    float4 next = make_float4(0.f,0.f,0.f,0.f);
    if (l > 0)      prev = *((const float4*)(g_u + (size_t)(r-1) * DINx) + c4);
    if (l < LL - 1) next = *((const float4*)(g_u + (size_t)(r+1) * DINx) + c4);
    float pv[4] = {prev.x, prev.y, prev.z, prev.w};
    float cv[4] = {cur.x,  cur.y,  cur.z,  cur.w};
    float nv[4] = {next.x, next.y, next.z, next.w};
    float ov[4];
#pragma unroll
    for (int j = 0; j < 4; j++) {
        float w0 = cw[(c+j)*3 + 0], w1 = cw[(c+j)*3 + 1], w2 = cw[(c+j)*3 + 2];
        float s = pv[j]*w0 + cv[j]*w1 + nv[j]*w2 + cb[c+j];
        ov[j] = 0.5f * s * (1.0f + erff(s * 0.70710678118654752f));
    }
    float4 o = make_float4(ov[0], ov[1], ov[2], ov[3]);
    *((float4*)(g_uc + (size_t)r * DINx) + c4) = o;
    split4_store(o, g_uc_hi, g_uc_lo, (size_t)r * DINx + c);
}

// ============================================================
// SSM scan v3: 128 CTAs = (b, h, p-half), 128 threads.
// thread (pl 0..31, nq 0..3) owns h[p, nq*16 .. nq*16+15] as 8 f32x2 pairs.
// B/C staged with 20-float chunk pitch; x read from fp32 g_uc.
// ============================================================
#define CHTOK 8
#define NCHS  (LL / CHTOK)
#define BCPITCH 160   /* floats per token: B 4 chunks * 20 + C 4 chunks * 20 */

__global__ __launch_bounds__(128, 1) void scan_kernel(
    const float* __restrict__ dt_bias, const float* __restrict__ A_log,
    const float* __restrict__ Ds)
{
    int blk = blockIdx.x;
    int b  = blk >> 4;
    int h  = (blk >> 1) & 7;
    int ph = blk & 1;
    int tid = threadIdx.x;
    int pl = tid >> 2, nq = tid & 3;
    int p  = ph * 32 + pl;
    size_t base = (size_t)b * LL;
    float Dsh  = Ds[h];
    float dtbh = dt_bias[h];
    float negA = -expf(A_log[h]);

    __shared__ __align__(16) float  sBC[2][CHTOK][BCPITCH];
    __shared__ __align__(16) float  sX [2][CHTOK][32];
    __shared__ __align__(8)  float2 sSc[2][CHTOK][2];

    int tokA = tid >> 5, qA = tid & 31;
    int tokB = (tid + 128) >> 5;                 // tokA + 4
    int dstA = (qA < 16) ? ((qA >> 2)*20 + (qA & 3)*4) : (80 + ((qA-16) >> 2)*20 + ((qA-16) & 3)*4);
    int srcA = (qA < 16) ? (8 + qA*4) : (72 + (qA-16)*4);
    int xtok = tid >> 3, xq = tid & 7;            // tid<64: 8 tok x 8 q

    u64 h2[8];
#pragma unroll
    for (int i = 0; i < 8; i++) h2[i] = 0ULL;

    float4 rA, rB, rX;
    float  rdt = 0.f, rde = 0.f;

#define CHUNK_LOAD(cidx) { size_t rb_ = base + (size_t)(cidx)*CHTOK; \
    rA = *(const float4*)(g_dbc + (rb_ + tokA)*XDIM + srcA); \
    rB = *(const float4*)(g_dbc + (rb_ + tokB)*XDIM + srcA); \
    if (tid < 64) rX = *(const float4*)(g_uc + (rb_ + xtok)*DINx + h*PP + ph*32 + xq*4); \
    if (tid >= 64 && tid < 64 + CHTOK) { int tk_ = tid - 64; \
        float lg_ = g_dbc[(rb_ + tk_)*XDIM + h] + dtbh; \
        float sp_ = (lg_ > 20.f) ? lg_ : log1pf(expf(lg_)); \
        rdt = sp_; rde = expf(negA * sp_); } }

#define CHUNK_STS(bufi) { *(float4*)&sBC[bufi][tokA][dstA] = rA; \
    *(float4*)&sBC[bufi][tokB][dstA] = rB; \
    if (tid < 64) *(float4*)&sX[bufi][xtok][xq*4] = rX; \
    if (tid >= 64 && tid < 64 + CHTOK) { int tk_ = tid - 64; \
        sSc[bufi][tk_][0] = make_float2(rdt, rdt); \
        sSc[bufi][tk_][1] = make_float2(rde, rde); } }

    CHUNK_LOAD(0)
    CHUNK_STS(0)

    for (int c = 0; c < NCHS; c++) {
        int cur = c & 1;
        __syncthreads();
        if (c + 1 < NCHS) { CHUNK_LOAD(c + 1) }
#pragma unroll
        for (int t = 0; t < CHTOK; t++) {
            F4U Bc[4], Cc[4];
#pragma unroll
            for (int j = 0; j < 4; j++) {
                Bc[j].f = *(const float4*)&sBC[cur][t][nq*20 + j*4];
                Cc[j].f = *(const float4*)&sBC[cur][t][80 + nq*20 + j*4];
            }
            float x = sX[cur][t][pl];
            F2U dt2, de2;
            dt2.f = sSc[cur][t][0];
            de2.f = sSc[cur][t][1];
            float dtx = dt2.f.x * x;
            u64 dtx2 = pack2(dtx, dtx);
            u64 dd2  = de2.u;

#pragma unroll
            for (int j = 0; j < 4; j++) {
                h2[2*j+0] = fma2(h2[2*j+0], dd2, mul2(dtx2, Bc[j].u.x));
                h2[2*j+1] = fma2(h2[2*j+1], dd2, mul2(dtx2, Bc[j].u.y));
            }
            u64 y0 = mul2(h2[0], Cc[0].u.x);
            u64 y1 = mul2(h2[2], Cc[1].u.x);
            u64 y2 = mul2(h2[4], Cc[2].u.x);
            u64 y3 = mul2(h2[6], Cc[3].u.x);
            y0 = fma2(h2[1], Cc[0].u.y, y0);
            y1 = fma2(h2[3], Cc[1].u.y, y1);
            y2 = fma2(h2[5], Cc[2].u.y, y2);
            y3 = fma2(h2[7], Cc[3].u.y, y3);
            float2 yf = unpack2(add2(add2(y0, y1), add2(y2, y3)));
            float y = yf.x + yf.y;
            y += __shfl_xor_sync(0xffffffffu, y, 1);
            y += __shfl_xor_sync(0xffffffffu, y, 2);
            if (nq == 0)
                g_y[(base + (size_t)c*CHTOK + t) * DINx + h*PP + p] = y + Dsh * x;
        }
        if (c + 1 < NCHS) { CHUNK_STS(cur ^ 1) }
    }
#undef CHUNK_LOAD
#undef CHUNK_STS
}

// ============================================================
extern "C" void kernel_launch(void* const* d_in, const int* in_sizes, int n_in,
                              void* d_out, int out_size)
{
    const float* src    = (const float*)d_in[0];
    const float* ln_w   = (const float*)d_in[1];
    const float* ln_b   = (const float*)d_in[2];
    const float* W_in   = (const float*)d_in[3];
    const float* conv_w = (const float*)d_in[4];
    const float* conv_b = (const float*)d_in[5];
    const float* W_xp   = (const float*)d_in[6];
    const float* dt_b   = (const float*)d_in[7];
    const float* A_log  = (const float*)d_in[8];
    const float* Ds     = (const float*)d_in[9];
    const float* oln_w  = (const float*)d_in[10];
    const float* oln_b  = (const float*)d_in[11];
    const float* W_out  = (const float*)d_in[12];
    float* out = (float*)d_out;
    (void)in_sizes; (void)n_in; (void)out_size;

    float *pu, *puc, *pdbc, *py;
    __nv_bfloat16 *pxh, *pxl, *puch, *pucl, *pylh, *pyll;
    __nv_bfloat16 *pw1h, *pw1l, *pw2h, *pw2l, *pw3h, *pw3l;
    cudaGetSymbolAddress((void**)&pu,   g_u);
    cudaGetSymbolAddress((void**)&puc,  g_uc);
    cudaGetSymbolAddress((void**)&pdbc, g_dbc);
    cudaGetSymbolAddress((void**)&py,   g_y);
    cudaGetSymbolAddress((void**)&pxh,  g_x_hi);
    cudaGetSymbolAddress((void**)&pxl,  g_x_lo);
    cudaGetSymbolAddress((void**)&puch, g_uc_hi);
    cudaGetSymbolAddress((void**)&pucl, g_uc_lo);
    cudaGetSymbolAddress((void**)&pylh, g_yl_hi);
    cudaGetSymbolAddress((void**)&pyll, g_yl_lo);
    cudaGetSymbolAddress((void**)&pw1h, g_wt1_hi);
    cudaGetSymbolAddress((void**)&pw1l, g_wt1_lo);
    cudaGetSymbolAddress((void**)&pw2h, g_wt2_hi);
    cudaGetSymbolAddress((void**)&pw2l, g_wt2_lo);
    cudaGetSymbolAddress((void**)&pw3h, g_wt3_hi);
    cudaGetSymbolAddress((void**)&pw3l, g_wt3_lo);

    // dynamic smem: 4*ASEG + 4*BSEG
    const int smem128 = 4*128*RPB + 4*128*RPB;   // 81920
    const int smem80  = 4*128*RPB + 4*80*RPB;    // 66560
    cudaFuncSetAttribute(gemm_mma<8,512,false>, cudaFuncAttributeMaxDynamicSharedMemorySize, smem128);
    cudaFuncSetAttribute(gemm_mma<5,136,false>, cudaFuncAttributeMaxDynamicSharedMemorySize, smem80);
    cudaFuncSetAttribute(gemm_mma<8,256,true>,  cudaFuncAttributeMaxDynamicSharedMemorySize, smem128);

    // launch order keeps gemm1 at profiled slot (index 3)
    prep_w_kernel<<<(DINx*DD + 255)/256, 256>>>(W_in, DD, DINx, DINx, pw1h, pw1l);
    prep_w_kernel<<<(XPAD*DINx + 255)/256, 256>>>(W_xp, DINx, XDIM, XPAD, pw2h, pw2l);
    ln_split_kernel<DD><<<NTOK/8, 256>>>(src, ln_w, ln_b, pxh, pxl);
    // g_u = x @ W_in  (M=16384, N=512, K=256)   <-- PROFILED SLOT
    gemm_mma<8,512,false><<<dim3(4, NTOK/128), 256, smem128>>>(pxh, pxl, pw1h, pw1l, nullptr, pu, DD, DINx);
    conv_gelu_kernel<<<(NTOK*DINx/4)/256, 256>>>(conv_w, conv_b);
    gemm_mma<5,136,false><<<dim3(2, NTOK/128), 256, smem80>>>(puch, pucl, pw2h, pw2l, nullptr, pdbc, DINx, XDIM);
    scan_kernel<<<128, 128>>>(dt_b, A_log, Ds);
    prep_w_kernel<<<(DD*DINx + 255)/256, 256>>>(W_out, DINx, DD, DD, pw3h, pw3l);
    ln_split_kernel<DINx><<<NTOK/8, 256>>>(py, oln_w, oln_b, pylh, pyll);
    gemm_mma<8,256,true><<<dim3(2, NTOK/128), 256, smem128>>>(pylh, pyll, pw3h, pw3l, src, out, DINx, DD);
}

// round 16
// speedup vs baseline: 1.5074x; 1.0129x over previous
#include <cuda_runtime.h>
#include <cuda_bf16.h>
#include <math.h>
#include <stdint.h>

#define BB   8
#define LL   2048
#define DD   256
#define DINx 512
#define NN   64
#define PP   64
#define HH   8
#define NTOK (BB*LL)
#define XDIM 136   /* H + 2N */
#define XPAD 160   /* padded N rows for xproj tensor GEMM (2 tiles of 80) */

typedef unsigned long long u64;

// ---- scratch (static device arrays; no allocation) ----
__device__ float g_u  [NTOK*DINx];
__device__ float g_uc [NTOK*DINx];
__device__ float g_dbc[NTOK*XDIM];
__device__ float g_y  [NTOK*DINx];

__device__ __nv_bfloat16 g_x_hi [NTOK*DD];
__device__ __nv_bfloat16 g_x_lo [NTOK*DD];
__device__ __nv_bfloat16 g_uc_hi[NTOK*DINx];
__device__ __nv_bfloat16 g_uc_lo[NTOK*DINx];
__device__ __nv_bfloat16 g_yl_hi[NTOK*DINx];
__device__ __nv_bfloat16 g_yl_lo[NTOK*DINx];

__device__ __nv_bfloat16 g_wt1_hi[DINx*DD];    // W_in^T  [512,256]
__device__ __nv_bfloat16 g_wt1_lo[DINx*DD];
__device__ __nv_bfloat16 g_wt2_hi[XPAD*DINx];  // W_xp^T  [160,512] (rows>=136 zero)
__device__ __nv_bfloat16 g_wt2_lo[XPAD*DINx];
__device__ __nv_bfloat16 g_wt3_hi[DD*DINx];    // W_out^T [256,512]
__device__ __nv_bfloat16 g_wt3_lo[DD*DINx];

// ---- f32x2 packed helpers (scan) ----
__device__ __forceinline__ u64 pack2(float lo, float hi) {
    u64 r; asm("mov.b64 %0, {%1,%2};" : "=l"(r) : "f"(lo), "f"(hi)); return r;
}
__device__ __forceinline__ float2 unpack2(u64 v) {
    float2 r; asm("mov.b64 {%0,%1}, %2;" : "=f"(r.x), "=f"(r.y) : "l"(v)); return r;
}
__device__ __forceinline__ u64 fma2(u64 a, u64 b, u64 c) {
    u64 d; asm("fma.rn.f32x2 %0, %1, %2, %3;" : "=l"(d) : "l"(a), "l"(b), "l"(c)); return d;
}
__device__ __forceinline__ u64 mul2(u64 a, u64 b) {
    u64 d; asm("mul.rn.f32x2 %0, %1, %2;" : "=l"(d) : "l"(a), "l"(b)); return d;
}
__device__ __forceinline__ u64 add2(u64 a, u64 b) {
    u64 d; asm("add.rn.f32x2 %0, %1, %2;" : "=l"(d) : "l"(a), "l"(b)); return d;
}
union F4U { float4 f; ulonglong2 u; };
union F2U { float2 f; u64 u; };

// ---- PTX helpers ----
__device__ __forceinline__ uint32_t smem_u32(const void* p) {
    uint32_t a;
    asm("{ .reg .u64 t; cvta.to.shared.u64 t, %1; cvt.u32.u64 %0, t; }" : "=r"(a) : "l"(p));
    return a;
}
__device__ __forceinline__ void cpasync16(uint32_t dst, const void* src) {
    asm volatile("cp.async.ca.shared.global [%0], [%1], 16;" :: "r"(dst), "l"(src));
}
#define CP_COMMIT() asm volatile("cp.async.commit_group;" ::: "memory")
#define CP_WAIT(n)  asm volatile("cp.async.wait_group %0;" :: "n"(n) : "memory")

__device__ __forceinline__ void ldsm4(uint32_t* r, uint32_t addr) {
    asm volatile("ldmatrix.sync.aligned.m8n8.x4.shared.b16 {%0,%1,%2,%3}, [%4];"
        : "=r"(r[0]), "=r"(r[1]), "=r"(r[2]), "=r"(r[3]) : "r"(addr));
}
__device__ __forceinline__ void ldsm2(uint32_t* r, uint32_t addr) {
    asm volatile("ldmatrix.sync.aligned.m8n8.x2.shared.b16 {%0,%1}, [%2];"
        : "=r"(r[0]), "=r"(r[1]) : "r"(addr));
}
__device__ __forceinline__ void mma_bf16(float* c, const uint32_t* a, const uint32_t* b) {
    asm volatile("mma.sync.aligned.m16n8k16.row.col.f32.bf16.bf16.f32 "
        "{%0,%1,%2,%3}, {%4,%5,%6,%7}, {%8,%9}, {%0,%1,%2,%3};"
        : "+f"(c[0]), "+f"(c[1]), "+f"(c[2]), "+f"(c[3])
        : "r"(a[0]), "r"(a[1]), "r"(a[2]), "r"(a[3]), "r"(b[0]), "r"(b[1]));
}

// ---- fp32 -> bf16 hi/lo split ----
__device__ __forceinline__ void split1(float v, __nv_bfloat16& h, __nv_bfloat16& l) {
    h = __float2bfloat16(v);
    l = __float2bfloat16(v - __bfloat162float(h));
}
__device__ __forceinline__ void split4_store(float4 v, __nv_bfloat16* hi, __nv_bfloat16* lo, size_t eidx) {
    __nv_bfloat16 h0,h1,h2,h3,l0,l1,l2,l3;
    split1(v.x,h0,l0); split1(v.y,h1,l1); split1(v.z,h2,l2); split1(v.w,h3,l3);
    __nv_bfloat162 ph0 = {h0,h1}, ph1 = {h2,h3}, pl0 = {l0,l1}, pl1 = {l2,l3};
    uint2 uh, ul;
    uh.x = *(uint32_t*)&ph0; uh.y = *(uint32_t*)&ph1;
    ul.x = *(uint32_t*)&pl0; ul.y = *(uint32_t*)&pl1;
    *(uint2*)(hi + eidx) = uh;
    *(uint2*)(lo + eidx) = ul;
}

// ============================================================
// LayerNorm: one warp per token; emits bf16 hi/lo split
// ============================================================
template<int D>
__global__ void ln_split_kernel(const float* __restrict__ x, const float* __restrict__ w,
                                const float* __restrict__ b,
                                __nv_bfloat16* __restrict__ ohi, __nv_bfloat16* __restrict__ olo)
{
    int gw   = (blockIdx.x * blockDim.x + threadIdx.x) >> 5;
    int lane = threadIdx.x & 31;
    if (gw >= NTOK) return;
    constexpr int V4 = D / 128;
    const float4* row = (const float4*)(x + (size_t)gw * D);
    float4 v[V4];
#pragma unroll
    for (int i = 0; i < V4; i++) v[i] = row[i*32 + lane];
    float s = 0.f;
#pragma unroll
    for (int i = 0; i < V4; i++) s += v[i].x + v[i].y + v[i].z + v[i].w;
#pragma unroll
    for (int o = 16; o; o >>= 1) s += __shfl_xor_sync(0xffffffffu, s, o);
    float m = s * (1.0f / D);
    float vs = 0.f;
#pragma unroll
    for (int i = 0; i < V4; i++) {
        float dx;
        dx = v[i].x - m; vs += dx*dx;
        dx = v[i].y - m; vs += dx*dx;
        dx = v[i].z - m; vs += dx*dx;
        dx = v[i].w - m; vs += dx*dx;
    }
#pragma unroll
    for (int o = 16; o; o >>= 1) vs += __shfl_xor_sync(0xffffffffu, vs, o);
    float rs = rsqrtf(vs * (1.0f / D) + 1e-5f);
    const float4* w4 = (const float4*)w;
    const float4* b4 = (const float4*)b;
#pragma unroll
    for (int i = 0; i < V4; i++) {
        float4 wv = w4[i*32 + lane], bv = b4[i*32 + lane], r;
        r.x = (v[i].x - m) * rs * wv.x + bv.x;
        r.y = (v[i].y - m) * rs * wv.y + bv.y;
        r.z = (v[i].z - m) * rs * wv.z + bv.z;
        r.w = (v[i].w - m) * rs * wv.w + bv.w;
        split4_store(r, ohi, olo, (size_t)gw * D + i*128 + lane*4);
    }
}

// ============================================================
// Weight prep: Wt[n,k] = W[k,n] (zero-pad n >= N), bf16 hi/lo
// ============================================================
__global__ void prep_w_kernel(const float* __restrict__ W, int K, int N, int NPAD,
                              __nv_bfloat16* __restrict__ hi, __nv_bfloat16* __restrict__ lo)
{
    int idx = blockIdx.x * blockDim.x + threadIdx.x;
    if (idx >= NPAD * K) return;
    int n = idx / K, k = idx - n * K;
    float v = (n < N) ? W[(size_t)k * N + n] : 0.f;
    __nv_bfloat16 h, l; split1(v, h, l);
    hi[idx] = h; lo[idx] = l;
}

// ============================================================
// HMMA bf16x3 GEMM: C[M,NVALID] = A[M,K] @ Bt[BN,K]^T (+res)
// CTA 128 x BN (BN = NFPW*16), 8 warps (4M x 2N), KC=32 chunks,
// cp.async double buffer, single sync/chunk, occupancy 2,
// product-major MMA ordering.
// ============================================================
#define KC2 32
#define RPB 80   /* (32+8) bf16 per row = 80 bytes, 16B aligned, conflict-free */

template<int NFPW, int NVALID, bool ADD_RES>
__global__ __launch_bounds__(256, 2) void gemm_mma(
    const __nv_bfloat16* __restrict__ Ahi, const __nv_bfloat16* __restrict__ Alo,
    const __nv_bfloat16* __restrict__ Bhi, const __nv_bfloat16* __restrict__ Blo,
    const float* __restrict__ res, float* __restrict__ C,
    int K, int NLD)
{
    constexpr int BN   = NFPW * 16;
    constexpr int ASEG = 128 * RPB;
    constexpr int BSEG = BN * RPB;
    constexpr int OFFB = 4 * ASEG;

    extern __shared__ __align__(16) char smem[];
    uint32_t sb = smem_u32(smem);

    int tid  = threadIdx.x;
    int lane = tid & 31, wid = tid >> 5;
    int wm = wid >> 1, wn = wid & 1;
    int m0 = blockIdx.y * 128;
    int n0 = blockIdx.x * BN;

    auto loadA = [&](int c, int buf) {
#pragma unroll
        for (int i = 0; i < 4; i++) {
            int e = tid + i*256;           // 1024 = 128 rows * 4 ch * 2 splits
            int ch = e & 3, row = (e >> 2) & 127, sp = e >> 9;
            const __nv_bfloat16* src = (sp ? Alo : Ahi) + (size_t)(m0 + row)*K + c*KC2 + ch*8;
            uint32_t dst = sb + (buf*2 + sp)*ASEG + row*RPB + ch*16;
            cpasync16(dst, src);
        }
    };
    auto loadB = [&](int c, int buf) {
        constexpr int TOT = BN * 4 * 2;
#pragma unroll
        for (int i = 0; i < (TOT + 255)/256; i++) {
            int e = tid + i*256;
            if ((TOT % 256 == 0) || e < TOT) {
                int ch = e & 3; int r2 = e >> 2;
                int sp = (r2 >= BN) ? 1 : 0; int row = r2 - sp*BN;
                const __nv_bfloat16* src = (sp ? Blo : Bhi) + (size_t)(n0 + row)*K + c*KC2 + ch*8;
                uint32_t dst = sb + OFFB + (buf*2 + sp)*BSEG + row*RPB + ch*16;
                cpasync16(dst, src);
            }
        }
    };

    float acc[2][NFPW][4];
#pragma unroll
    for (int mf = 0; mf < 2; mf++)
#pragma unroll
        for (int nf = 0; nf < NFPW; nf++)
#pragma unroll
            for (int q = 0; q < 4; q++) acc[mf][nf][q] = 0.f;

    int g = lane >> 3;
    int laneA = ((lane & 7) + ((g & 1) << 3)) * RPB + ((g >> 1) << 4);
    int laneB = ((lane & 7) + ((g >> 1) << 3)) * RPB + ((g & 1) << 4);
    int nwbase = wn * NFPW * 8;

    const int NCH = K / KC2;
    loadA(0, 0); loadB(0, 0); CP_COMMIT();

    for (int c = 0; c < NCH; c++) {
        int buf = c & 1;
        CP_WAIT(0);
        __syncthreads();
        if (c + 1 < NCH) { loadA(c+1, buf^1); loadB(c+1, buf^1); CP_COMMIT(); }
#pragma unroll
        for (int ks = 0; ks < 2; ks++) {
            uint32_t a[2][2][4];
#pragma unroll
            for (int mf = 0; mf < 2; mf++)
#pragma unroll
                for (int sp = 0; sp < 2; sp++)
                    ldsm4(a[mf][sp], sb + (buf*2 + sp)*ASEG + (wm*32 + mf*16)*RPB + laneA + ks*32);
#pragma unroll
            for (int np = 0; np < NFPW/2; np++) {
                uint32_t bh[4], bl[4];
                uint32_t ab = sb + OFFB + (buf*2 + 0)*BSEG + (nwbase + np*16)*RPB + laneB + ks*32;
                ldsm4(bh, ab);
                ldsm4(bl, ab + BSEG);
                // product-major: 4 distinct accumulators between revisits
#pragma unroll
                for (int mf = 0; mf < 2; mf++)
#pragma unroll
                    for (int q = 0; q < 2; q++)
                        mma_bf16(acc[mf][np*2+q], a[mf][0], bh + q*2);
#pragma unroll
                for (int mf = 0; mf < 2; mf++)
#pragma unroll
                    for (int q = 0; q < 2; q++)
                        mma_bf16(acc[mf][np*2+q], a[mf][0], bl + q*2);
#pragma unroll
                for (int mf = 0; mf < 2; mf++)
#pragma unroll
                    for (int q = 0; q < 2; q++)
                        mma_bf16(acc[mf][np*2+q], a[mf][1], bh + q*2);
            }
            if (NFPW & 1) {
                int nf = NFPW - 1;
                uint32_t bh[2], bl[2];
                uint32_t ab = sb + OFFB + (buf*2 + 0)*BSEG + (nwbase + nf*8)*RPB + laneB + ks*32;
                ldsm2(bh, ab);
                ldsm2(bl, ab + BSEG);
#pragma unroll
                for (int mf = 0; mf < 2; mf++) mma_bf16(acc[mf][nf], a[mf][0], bh);
#pragma unroll
                for (int mf = 0; mf < 2; mf++) mma_bf16(acc[mf][nf], a[mf][0], bl);
#pragma unroll
                for (int mf = 0; mf < 2; mf++) mma_bf16(acc[mf][nf], a[mf][1], bh);
            }
        }
    }

    // epilogue (registers only)
    int rbase = m0 + wm*32 + (lane >> 2);
    int colb  = n0 + nwbase + (lane & 3)*2;
#pragma unroll
    for (int mf = 0; mf < 2; mf++) {
#pragma unroll
        for (int nf = 0; nf < NFPW; nf++) {
            int col = colb + nf*8;
            if ((NVALID % BN == 0) || col < NVALID) {
                int ra = rbase + mf*16;
                size_t i0 = (size_t)ra * NLD + col;
                size_t i1 = (size_t)(ra + 8) * NLD + col;
                float2 v0 = make_float2(acc[mf][nf][0], acc[mf][nf][1]);
                float2 v1 = make_float2(acc[mf][nf][2], acc[mf][nf][3]);
                if (ADD_RES) {
                    float2 r0 = *(const float2*)(res + i0);
                    float2 r1 = *(const float2*)(res + i1);
                    v0.x += r0.x; v0.y += r0.y;
                    v1.x += r1.x; v1.y += r1.y;
                }
                *(float2*)(C + i0) = v0;
                *(float2*)(C + i1) = v1;
            }
        }
    }
}

// ============================================================
// depthwise conv3 (SAME) + bias + exact GELU
// writes fp32 g_uc (for the scan) AND bf16 hi/lo (for xproj GEMM)
// ============================================================
__global__ void conv_gelu_kernel(const float* __restrict__ cw, const float* __restrict__ cb)
{
    int idx = blockIdx.x * blockDim.x + threadIdx.x;  // NTOK*DINx/4 items
    int c4 = idx & (DINx/4 - 1);
    int r  = idx >> 7;
    int l  = r & (LL - 1);
    int c  = c4 * 4;
    float4 cur  = *((const float4*)(g_u + (size_t)r * DINx) + c4);
    float4 prev = make_float4(0.f,0.f,0.f,0.f);
    float4 next = make_float4(0.f,0.f,0.f,0.f);
    if (l > 0)      prev = *((const float4*)(g_u + (size_t)(r-1) * DINx) + c4);
    if (l < LL - 1) next = *((const float4*)(g_u + (size_t)(r+1) * DINx) + c4);
    float pv[4] = {prev.x, prev.y, prev.z, prev.w};
    float cv[4] = {cur.x,  cur.y,  cur.z,  cur.w};
    float nv[4] = {next.x, next.y, next.z, next.w};
    float ov[4];
#pragma unroll
    for (int j = 0; j < 4; j++) {
        float w0 = cw[(c+j)*3 + 0], w1 = cw[(c+j)*3 + 1], w2 = cw[(c+j)*3 + 2];
        float s = pv[j]*w0 + cv[j]*w1 + nv[j]*w2 + cb[c+j];
        ov[j] = 0.5f * s * (1.0f + erff(s * 0.70710678118654752f));
    }
    float4 o = make_float4(ov[0], ov[1], ov[2], ov[3]);
    *((float4*)(g_uc + (size_t)r * DINx) + c4) = o;
    split4_store(o, g_uc_hi, g_uc_lo, (size_t)r * DINx + c);
}

// ============================================================
// SSM scan v5: 128 CTAs = (b, h, p-half), 256 threads (2 warps/SMSP).
// thread (pl 0..31, nq 0..7) owns h[p, nq*8 .. nq*8+7] as 4 f32x2 pairs.
// B/C staged with 12-float nq-block pitch (conflict-free, 16B aligned).
// x from fp32 g_uc. Double-buffered, 8 tok/chunk.
// ============================================================
#define CHTOK 8
#define NCHS  (LL / CHTOK)
#define BCPITCH 192   /* floats per token: B 8 blocks * 12 + C 8 blocks * 12 */

__global__ __launch_bounds__(256, 1) void scan_kernel(
    const float* __restrict__ dt_bias, const float* __restrict__ A_log,
    const float* __restrict__ Ds)
{
    int blk = blockIdx.x;
    int b  = blk >> 4;
    int h  = (blk >> 1) & 7;
    int ph = blk & 1;
    int tid = threadIdx.x;
    int pl = tid >> 3, nq = tid & 7;     // pl 0..31, nq 0..7
    int p  = ph * 32 + pl;
    size_t base = (size_t)b * LL;
    float Dsh  = Ds[h];
    float dtbh = dt_bias[h];
    float negA = -expf(A_log[h]);

    __shared__ __align__(16) float  sBC[2][CHTOK][BCPITCH];
    __shared__ __align__(16) float  sX [2][CHTOK][32];
    __shared__ __align__(8)  float2 sSc[2][CHTOK][2];

    // loaders: BC = 8 tok * 32 chunks(16B) = 256 -> one per thread
    int tokA = tid >> 5, qA = tid & 31;
    int q2   = (qA < 16) ? qA : (qA - 16);
    int dstA = ((qA < 16) ? 0 : 96) + (q2 >> 1)*12 + (q2 & 1)*4;
    int srcA = ((qA < 16) ? 8 : 72) + q2*4;
    int xtok = tid >> 3, xq = tid & 7;            // tid<64: 8 tok x 8 q

    u64 h2[4];
#pragma unroll
    for (int i = 0; i < 4; i++) h2[i] = 0ULL;

    float4 rA, rX;
    float  rdt = 0.f, rde = 0.f;

#define CHUNK_LOAD(cidx) { size_t rb_ = base + (size_t)(cidx)*CHTOK; \
    rA = *(const float4*)(g_dbc + (rb_ + tokA)*XDIM + srcA); \
    if (tid < 64) rX = *(const float4*)(g_uc + (rb_ + xtok)*DINx + h*PP + ph*32 + xq*4); \
    if (tid >= 64 && tid < 64 + CHTOK) { int tk_ = tid - 64; \
        float lg_ = g_dbc[(rb_ + tk_)*XDIM + h] + dtbh; \
        float sp_ = (lg_ > 20.f) ? lg_ : log1pf(expf(lg_)); \
        rdt = sp_; rde = expf(negA * sp_); } }

#define CHUNK_STS(bufi) { *(float4*)&sBC[bufi][tokA][dstA] = rA; \
    if (tid < 64) *(float4*)&sX[bufi][xtok][xq*4] = rX; \
    if (tid >= 64 && tid < 64 + CHTOK) { int tk_ = tid - 64; \
        sSc[bufi][tk_][0] = make_float2(rdt, rdt); \
        sSc[bufi][tk_][1] = make_float2(rde, rde); } }

    CHUNK_LOAD(0)
    CHUNK_STS(0)

    for (int c = 0; c < NCHS; c++) {
        int cur = c & 1;
        __syncthreads();
        if (c + 1 < NCHS) { CHUNK_LOAD(c + 1) }
#pragma unroll
        for (int t = 0; t < CHTOK; t++) {
            F4U B0, B1, C0, C1;
            B0.f = *(const float4*)&sBC[cur][t][nq*12];
            B1.f = *(const float4*)&sBC[cur][t][nq*12 + 4];
            C0.f = *(const float4*)&sBC[cur][t][96 + nq*12];
            C1.f = *(const float4*)&sBC[cur][t][96 + nq*12 + 4];
            float x = sX[cur][t][pl];
            F2U dt2, de2;
            dt2.f = sSc[cur][t][0];
            de2.f = sSc[cur][t][1];
            float dtx = dt2.f.x * x;
            u64 dtx2 = pack2(dtx, dtx);
            u64 dd2  = de2.u;

            h2[0] = fma2(h2[0], dd2, mul2(dtx2, B0.u.x));
            h2[1] = fma2(h2[1], dd2, mul2(dtx2, B0.u.y));
            h2[2] = fma2(h2[2], dd2, mul2(dtx2, B1.u.x));
            h2[3] = fma2(h2[3], dd2, mul2(dtx2, B1.u.y));

            u64 y0 = mul2(h2[0], C0.u.x);
            u64 y1 = mul2(h2[2], C1.u.x);
            y0 = fma2(h2[1], C0.u.y, y0);
            y1 = fma2(h2[3], C1.u.y, y1);
            float2 yf = unpack2(add2(y0, y1));
            float y = yf.x + yf.y;
            y += __shfl_xor_sync(0xffffffffu, y, 1);
            y += __shfl_xor_sync(0xffffffffu, y, 2);
            y += __shfl_xor_sync(0xffffffffu, y, 4);
            if (nq == 0)
                g_y[(base + (size_t)c*CHTOK + t) * DINx + h*PP + p] = y + Dsh * x;
        }
        if (c + 1 < NCHS) { CHUNK_STS(cur ^ 1) }
    }
#undef CHUNK_LOAD
#undef CHUNK_STS
}

// ============================================================
extern "C" void kernel_launch(void* const* d_in, const int* in_sizes, int n_in,
                              void* d_out, int out_size)
{
    const float* src    = (const float*)d_in[0];
    const float* ln_w   = (const float*)d_in[1];
    const float* ln_b   = (const float*)d_in[2];
    const float* W_in   = (const float*)d_in[3];
    const float* conv_w = (const float*)d_in[4];
    const float* conv_b = (const float*)d_in[5];
    const float* W_xp   = (const float*)d_in[6];
    const float* dt_b   = (const float*)d_in[7];
    const float* A_log  = (const float*)d_in[8];
    const float* Ds     = (const float*)d_in[9];
    const float* oln_w  = (const float*)d_in[10];
    const float* oln_b  = (const float*)d_in[11];
    const float* W_out  = (const float*)d_in[12];
    float* out = (float*)d_out;
    (void)in_sizes; (void)n_in; (void)out_size;

    float *pu, *puc, *pdbc, *py;
    __nv_bfloat16 *pxh, *pxl, *puch, *pucl, *pylh, *pyll;
    __nv_bfloat16 *pw1h, *pw1l, *pw2h, *pw2l, *pw3h, *pw3l;
    cudaGetSymbolAddress((void**)&pu,   g_u);
    cudaGetSymbolAddress((void**)&puc,  g_uc);
    cudaGetSymbolAddress((void**)&pdbc, g_dbc);
    cudaGetSymbolAddress((void**)&py,   g_y);
    cudaGetSymbolAddress((void**)&pxh,  g_x_hi);
    cudaGetSymbolAddress((void**)&pxl,  g_x_lo);
    cudaGetSymbolAddress((void**)&puch, g_uc_hi);
    cudaGetSymbolAddress((void**)&pucl, g_uc_lo);
    cudaGetSymbolAddress((void**)&pylh, g_yl_hi);
    cudaGetSymbolAddress((void**)&pyll, g_yl_lo);
    cudaGetSymbolAddress((void**)&pw1h, g_wt1_hi);
    cudaGetSymbolAddress((void**)&pw1l, g_wt1_lo);
    cudaGetSymbolAddress((void**)&pw2h, g_wt2_hi);
    cudaGetSymbolAddress((void**)&pw2l, g_wt2_lo);
    cudaGetSymbolAddress((void**)&pw3h, g_wt3_hi);
    cudaGetSymbolAddress((void**)&pw3l, g_wt3_lo);

    // dynamic smem: 4*ASEG + 4*BSEG
    const int smem128 = 4*128*RPB + 4*128*RPB;   // 81920
    const int smem80  = 4*128*RPB + 4*80*RPB;    // 66560
    cudaFuncSetAttribute(gemm_mma<8,512,false>, cudaFuncAttributeMaxDynamicSharedMemorySize, smem128);
    cudaFuncSetAttribute(gemm_mma<5,136,false>, cudaFuncAttributeMaxDynamicSharedMemorySize, smem80);
    cudaFuncSetAttribute(gemm_mma<8,256,true>,  cudaFuncAttributeMaxDynamicSharedMemorySize, smem128);

    // launch order keeps gemm1 at profiled slot (index 3)
    prep_w_kernel<<<(DINx*DD + 255)/256, 256>>>(W_in, DD, DINx, DINx, pw1h, pw1l);
    prep_w_kernel<<<(XPAD*DINx + 255)/256, 256>>>(W_xp, DINx, XDIM, XPAD, pw2h, pw2l);
    ln_split_kernel<DD><<<NTOK/8, 256>>>(src, ln_w, ln_b, pxh, pxl);
    // g_u = x @ W_in  (M=16384, N=512, K=256)   <-- PROFILED SLOT
    gemm_mma<8,512,false><<<dim3(4, NTOK/128), 256, smem128>>>(pxh, pxl, pw1h, pw1l, nullptr, pu, DD, DINx);
    conv_gelu_kernel<<<(NTOK*DINx/4)/256, 256>>>(conv_w, conv_b);
    gemm_mma<5,136,false><<<dim3(2, NTOK/128), 256, smem80>>>(puch, pucl, pw2h, pw2l, nullptr, pdbc, DINx, XDIM);
    scan_kernel<<<128, 256>>>(dt_b, A_log, Ds);
    prep_w_kernel<<<(DD*DINx + 255)/256, 256>>>(W_out, DINx, DD, DD, pw3h, pw3l);
    ln_split_kernel<DINx><<<NTOK/8, 256>>>(py, oln_w, oln_b, pylh, pyll);
    gemm_mma<8,256,true><<<dim3(2, NTOK/128), 256, smem128>>>(pylh, pyll, pw3h, pw3l, src, out, DINx, DD);
}